// round 2
// baseline (speedup 1.0000x reference)
#include <cuda_runtime.h>

// Gate table: [channel][pair k][ {cos(tz/2), sin(tz/2), cos(tx/2), sin(tx/2)} ]
__device__ float g_gates[4][8][4];

__global__ void quanv_prep_kernel(const float* __restrict__ qp) {
    int t = threadIdx.x;            // 0..31
    if (t < 32) {
        int ch = t >> 3, k = t & 7;
        float tz = qp[ch * 16 + 2 * k];
        float tx = qp[ch * 16 + 2 * k + 1];
        g_gates[ch][k][0] = cosf(0.5f * tz);
        g_gates[ch][k][1] = sinf(0.5f * tz);
        g_gates[ch][k][2] = cosf(0.5f * tx);
        g_gates[ch][k][3] = sinf(0.5f * tx);
    }
}

// Controlled-RZ: for indices with ctrl bit set, multiply by (cz, -sz) if tgt=0
// else (cz, +sz).  (Rz(t) = diag(e^{-it/2}, e^{+it/2}))
template <int N, int MC, int MT>
__device__ __forceinline__ void crz(float (&re)[N], float (&im)[N], float cz, float sz) {
#pragma unroll
    for (int i = 0; i < N; i++) {
        if (i & MC) {
            float ci = (i & MT) ? sz : -sz;
            float r = re[i] * cz - im[i] * ci;
            float m = re[i] * ci + im[i] * cz;
            re[i] = r; im[i] = m;
        }
    }
}

// Controlled-RX: for indices with ctrl bit set, mix (tgt=0, tgt=1) pair with
// [[c, -is], [-is, c]].
template <int N, int MC, int MT>
__device__ __forceinline__ void crx(float (&re)[N], float (&im)[N], float cx, float sx) {
#pragma unroll
    for (int i = 0; i < N; i++) {
        if ((i & MC) && !(i & MT)) {
            int j = i | MT;
            float r0 = re[i], m0 = im[i], r1 = re[j], m1 = im[j];
            re[i] = cx * r0 + sx * m1;
            im[i] = cx * m0 - sx * r1;
            re[j] = cx * r1 + sx * m0;
            im[j] = cx * m1 - sx * r0;
        }
    }
}

// One thread = one (b, r, c, ch) simulation.
// Global amplitude index convention: qubit q -> bit (8 - q).
// Group A = qubits 0..3 (16 amps, local bit j -> qubit 3-j).
// Group B = qubits 4..8 (32 amps, local bit j -> qubit 8-j).
// Pairs (ctrl,tgt): k0..2 live in A, k3..6 live in B, k7=(4,0) couples them and
// is folded into the final measurement.
__global__ void quanv_kernel(const float* __restrict__ x, float* __restrict__ out,
                             int total) {
    int idx = blockIdx.x * blockDim.x + threadIdx.x;
    if (idx >= total) return;

    int ch = idx & 3;
    int sp_idx = idx >> 2;          // b*900 + h*30 + w
    int w = sp_idx % 30;
    int h = (sp_idx / 30) % 30;
    int b = sp_idx / 900;

    if (h == 0 || h == 29 || w == 0 || w == 29) {
        out[idx] = 0.0f;            // zero padding border
        return;
    }
    int r = h - 1, c = w - 1;

    // --- per-qubit RX factors from the patch ---
    // angle = 2*pi*p - pi ; half = pi*p - pi/2 ; cos(half) = sin(pi p),
    // sin(half) = -cos(pi p)
    float cq[9], sq[9];
    const float* xb = x + b * 2700;  // 30*30*3
#pragma unroll
    for (int dr = 0; dr < 3; dr++) {
#pragma unroll
        for (int dc = 0; dc < 3; dc++) {
            const float* px = xb + ((r + dr) * 30 + (c + dc)) * 3;
            float p = (px[0] + px[1] + px[2]) * (1.0f / 3.0f);
            float sp, cp;
            sincospif(p, &sp, &cp);
            cq[dr * 3 + dc] = sp;
            sq[dr * 3 + dc] = -cp;
        }
    }

    const float (*gg)[4] = g_gates[ch];

    // ---------------- Group B: qubits 4..8, 32 amplitudes ----------------
    float Br[32], Bi[32];
#pragma unroll
    for (int i = 0; i < 32; i++) {
        float mag = 1.0f;
        int pop = 0;
#pragma unroll
        for (int j = 0; j < 5; j++) {
            int q = 8 - j;                 // bit j of i -> qubit 8-j
            if ((i >> j) & 1) { mag *= sq[q]; pop++; }
            else              { mag *= cq[q]; }
        }
        pop &= 3;                          // phase (-i)^pop
        Br[i] = (pop == 0) ? mag : ((pop == 2) ? -mag : 0.0f);
        Bi[i] = (pop == 1) ? -mag : ((pop == 3) ? mag : 0.0f);
    }
    // k=3 (8,7): ctrl qubit8 -> bit0 (1), tgt qubit7 -> bit1 (2)
    crz<32, 1, 2>(Br, Bi, gg[3][0], gg[3][1]);
    crx<32, 1, 2>(Br, Bi, gg[3][2], gg[3][3]);
    // k=4 (5,4): ctrl qubit5 -> bit3 (8), tgt qubit4 -> bit4 (16)
    crz<32, 8, 16>(Br, Bi, gg[4][0], gg[4][1]);
    crx<32, 8, 16>(Br, Bi, gg[4][2], gg[4][3]);
    // k=5 (7,6): ctrl qubit7 -> bit1 (2), tgt qubit6 -> bit2 (4)
    crz<32, 2, 4>(Br, Bi, gg[5][0], gg[5][1]);
    crx<32, 2, 4>(Br, Bi, gg[5][2], gg[5][3]);
    // k=6 (6,4): ctrl qubit6 -> bit2 (4), tgt qubit4 -> bit4 (16)
    crz<32, 4, 16>(Br, Bi, gg[6][0], gg[6][1]);
    crx<32, 4, 16>(Br, Bi, gg[6][2], gg[6][3]);

    float nB0 = 0.0f, nB1 = 0.0f;   // norm with qubit4 = 0 / 1 (bit4 of i)
#pragma unroll
    for (int i = 0; i < 32; i++) {
        float p2 = Br[i] * Br[i] + Bi[i] * Bi[i];
        if (i & 16) nB1 += p2; else nB0 += p2;
    }

    // ---------------- Group A: qubits 0..3, 16 amplitudes ----------------
    float Ar[16], Ai[16];
#pragma unroll
    for (int i = 0; i < 16; i++) {
        float mag = 1.0f;
        int pop = 0;
#pragma unroll
        for (int j = 0; j < 4; j++) {
            int q = 3 - j;                 // bit j of i -> qubit 3-j
            if ((i >> j) & 1) { mag *= sq[q]; pop++; }
            else              { mag *= cq[q]; }
        }
        pop &= 3;
        Ar[i] = (pop == 0) ? mag : ((pop == 2) ? -mag : 0.0f);
        Ai[i] = (pop == 1) ? -mag : ((pop == 3) ? mag : 0.0f);
    }
    // k=0 (1,0): ctrl qubit1 -> bit2 (4), tgt qubit0 -> bit3 (8)
    crz<16, 4, 8>(Ar, Ai, gg[0][0], gg[0][1]);
    crx<16, 4, 8>(Ar, Ai, gg[0][2], gg[0][3]);
    // k=1 (3,2): ctrl qubit3 -> bit0 (1), tgt qubit2 -> bit1 (2)
    crz<16, 1, 2>(Ar, Ai, gg[1][0], gg[1][1]);
    crx<16, 1, 2>(Ar, Ai, gg[1][2], gg[1][3]);
    // k=2 (2,0): ctrl qubit2 -> bit1 (2), tgt qubit0 -> bit3 (8)
    crz<16, 2, 8>(Ar, Ai, gg[2][0], gg[2][1]);
    crx<16, 2, 8>(Ar, Ai, gg[2][2], gg[2][3]);

    // dA = signed norm over qubit0 (bit3) before the final coupled pair
    float dA = 0.0f;
#pragma unroll
    for (int i = 0; i < 16; i++) {
        float p2 = Ar[i] * Ar[i] + Ai[i] * Ai[i];
        dA += (i & 8) ? -p2 : p2;
    }

    // Final pair k=7 (ctrl qubit4 in B, tgt qubit0 in A):
    // on the q4=1 branch, apply Rz(t14) then Rx(t15) to qubit0 of A.
    float cz = gg[7][0], sz = gg[7][1], cx = gg[7][2], sx = gg[7][3];
    float dA2 = 0.0f;
#pragma unroll
    for (int a0 = 0; a0 < 8; a0++) {
        int a1 = a0 | 8;
        // Rz: tgt=0 amp *= (cz, -sz); tgt=1 amp *= (cz, +sz)
        float v0r = Ar[a0] * cz + Ai[a0] * sz;
        float v0i = Ai[a0] * cz - Ar[a0] * sz;
        float v1r = Ar[a1] * cz - Ai[a1] * sz;
        float v1i = Ai[a1] * cz + Ar[a1] * sz;
        // Rx mix
        float n0r = cx * v0r + sx * v1i;
        float n0i = cx * v0i - sx * v1r;
        float n1r = cx * v1r + sx * v0i;
        float n1i = cx * v1i - sx * v0r;
        dA2 += (n0r * n0r + n0i * n0i) - (n1r * n1r + n1i * n1i);
    }

    float z = nB0 * dA + nB1 * dA2;
    out[idx] = 0.5f * (z + 1.0f);
}

extern "C" void kernel_launch(void* const* d_in, const int* in_sizes, int n_in,
                              void* d_out, int out_size) {
    const float* x = (const float*)d_in[0];       // (8,30,30,3) float32
    const float* qp = (const float*)d_in[1];      // (4,16) float32
    float* out = (float*)d_out;                   // (8,30,30,4) float32

    quanv_prep_kernel<<<1, 32>>>(qp);
    int total = out_size;                         // 28800
    int threads = 256;
    int blocks = (total + threads - 1) / threads;
    quanv_kernel<<<blocks, threads>>>(x, out, total);
}